// round 3
// baseline (speedup 1.0000x reference)
#include <cuda_runtime.h>
#include <math.h>

#define Bn 8
#define Hh 640
#define Ww 640
#define HW (Hh*Ww)          // 409600
#define HW4 (HW/4)
#define NCH 10
#define NKER 5
#define NL 16
#define NEGINF (-1e30f)

// ---------------- scratch ----------------
__device__ unsigned g_negbits[Bn*HW];
__device__ int      g_negcount[Bn];
__device__ int      g_npos[Bn];
__device__ float    g_posSum[Bn], g_posSum2[Bn];
__device__ float    g_negselSum[Bn];
__device__ float    g_kInter[Bn*NKER], g_kU1[Bn*NKER], g_kU2[Bn*NKER];
__device__ float    g_embCnt[Bn][NL];
__device__ float    g_embSum[Bn][NL][4];
__device__ float    g_lvSum[Bn];

__device__ __forceinline__ float sigm(float x){ return 1.0f/(1.0f+expf(-x)); }

// ---------------- zero ----------------
__global__ void k_zero(){
    int idx = threadIdx.x;
    if (idx < Bn){
        g_negcount[idx]=0; g_npos[idx]=0; g_posSum[idx]=0.f; g_posSum2[idx]=0.f;
        g_negselSum[idx]=0.f; g_lvSum[idx]=0.f;
    }
    if (idx < Bn*NKER){ g_kInter[idx]=0.f; g_kU1[idx]=0.f; g_kU2[idx]=0.f; }
    if (idx < Bn*NL) ((float*)g_embCnt)[idx]=0.f;
    for (int i = idx; i < Bn*NL*4; i += 256) ((float*)g_embSum)[i]=0.f;
}

// ------- fused dilate (sigmoid-of-max) + OHEM stats + staged compaction ----
// grid (20,20,Bn), block (32,8). Tile 32x32, halo 4.
__global__ void k_dilstats(const float* __restrict__ pred,
                           const float* __restrict__ gt,
                           const float* __restrict__ tm){
    __shared__ float sIn[40][41];
    __shared__ float sHm[40][33];
    __shared__ unsigned sNeg[1024];
    __shared__ int sCnt, sBase;
    __shared__ float sR0[8], sR1[8], sR2[8];
    int b = blockIdx.z;
    int gx0 = blockIdx.x*32 - 4, gy0 = blockIdx.y*32 - 4;
    int tid = threadIdx.y*32 + threadIdx.x;
    int lane = tid & 31, wid = tid >> 5;
    const float* p0 = pred + b*NCH*HW;

    if (tid == 0) sCnt = 0;
    for (int idx = tid; idx < 1600; idx += 256){
        int r = idx/40, c = idx - 40*r;
        int gy = gy0 + r, gx = gx0 + c;
        sIn[r][c] = (gy>=0 && gy<Hh && gx>=0 && gx<Ww) ? p0[gy*Ww + gx] : NEGINF;
    }
    __syncthreads();
    for (int idx = tid; idx < 1280; idx += 256){
        int r = idx >> 5, c = idx & 31;
        float m = sIn[r][c];
        #pragma unroll
        for (int j=1;j<9;j++) m = fmaxf(m, sIn[r][c+j]);
        sHm[r][c] = m;
    }
    __syncthreads();

    int pc = 0; float ps = 0.f, ps2 = 0.f;
    #pragma unroll
    for (int k=0;k<4;k++){
        int r = threadIdx.y*4 + k;
        int c = threadIdx.x;
        float m = sHm[r][c];
        #pragma unroll
        for (int j=1;j<9;j++) m = fmaxf(m, sHm[r+j][c]);
        float v = sigm(m);                  // sigmoid after max (monotone)
        int gy = gy0 + 4 + r, gx = gx0 + 4 + c;
        int gi = b*HW + gy*Ww + gx;
        float g  = gt[gi];
        float mm = tm[gi];
        bool isPos = (g > 0.5f) && (mm > 0.5f);
        bool isNeg = (g <= 0.5f) && (mm > 0.5f);
        if (isPos){ pc++; ps += v; ps2 += v*v; }
        unsigned ball = __ballot_sync(0xffffffffu, isNeg);
        if (isNeg){
            int rank = __popc(ball & ((1u<<lane)-1u));
            int leader = __ffs(ball)-1;
            int base = 0;
            if (lane == leader) base = atomicAdd(&sCnt, __popc(ball));
            base = __shfl_sync(ball, base, leader);
            sNeg[base + rank] = __float_as_uint(v);
        }
    }
    // warp reduce pos stats
    #pragma unroll
    for (int o=16;o;o>>=1){
        pc  += __shfl_down_sync(0xffffffffu, pc, o);
        ps  += __shfl_down_sync(0xffffffffu, ps, o);
        ps2 += __shfl_down_sync(0xffffffffu, ps2, o);
    }
    if (lane == 0){ sR0[wid]=(float)pc; sR1[wid]=ps; sR2[wid]=ps2; }
    __syncthreads();        // covers sNeg, sCnt, sR*
    if (tid == 0){
        float a=0,bb=0,cc=0;
        #pragma unroll
        for (int w=0;w<8;w++){ a+=sR0[w]; bb+=sR1[w]; cc+=sR2[w]; }
        if (a  != 0.f) atomicAdd(&g_npos[b], (int)a);
        if (bb != 0.f) atomicAdd(&g_posSum[b], bb);
        if (cc != 0.f) atomicAdd(&g_posSum2[b], cc);
        sBase = atomicAdd(&g_negcount[b], sCnt);
    }
    __syncthreads();
    int cnt = sCnt, base = sBase;
    unsigned* dst = g_negbits + b*HW + base;
    for (int i = tid; i < cnt; i += 256) dst[i] = sNeg[i];
}

// ---------- single-launch 3-level radix select with per-bin sumsq ----------
// grid Bn x 1024
__global__ void k_selectAll(){
    __shared__ unsigned hC[4096];
    __shared__ float    hQ[4096];
    __shared__ unsigned scC[1024];
    __shared__ float    scQ[1024];
    __shared__ unsigned sPrefix;
    __shared__ int      sK;
    __shared__ float    sNegsel;
    int b = blockIdx.x;
    int t = threadIdx.x;
    int cnt = g_negcount[b];
    int k0 = 3*g_npos[b]; if (k0 > cnt) k0 = cnt;
    if (t == 0){ sK = k0; sNegsel = 0.f; sPrefix = 0u; }
    __syncthreads();
    if (k0 <= 0){
        if (t == 0) g_negselSum[b] = 0.f;
        return;
    }
    const unsigned* nb = g_negbits + b*HW;
    for (int level = 1; level <= 3; level++){
        int K = sK;                       // stable: last write before prev level-end sync
        unsigned pfx = sPrefix;
        for (int i=t;i<4096;i+=1024){ hC[i]=0u; hQ[i]=0.f; }
        __syncthreads();
        // histogram with warp fast-path for uniform bins
        for (int j = t; j - t < cnt; j += 1024){
            bool in = j < cnt;
            unsigned bits = in ? nb[j] : 0u;
            unsigned bin = 0; bool ok = false;
            if (in){
                if (level == 1){ bin = bits >> 20; ok = true; }
                else if (level == 2){ ok = (bits>>20)==(pfx>>20); bin = (bits>>8)&0xFFFu; }
                else { ok = (bits>>8)==(pfx>>8); bin = bits & 0xFFu; }
            }
            float v = __uint_as_float(bits);
            float q = v*v;
            unsigned key = ok ? bin : 0xFFFFFFFFu;
            unsigned grp = __match_any_sync(0xffffffffu, key);
            if (grp == 0xffffffffu){
                if (ok){
                    #pragma unroll
                    for (int o=16;o;o>>=1) q += __shfl_down_sync(0xffffffffu, q, o);
                    if ((t & 31) == 0){ atomicAdd(&hC[bin], 32u); atomicAdd(&hQ[bin], q); }
                }
            } else if (ok){
                atomicAdd(&hC[bin], 1u); atomicAdd(&hQ[bin], q);
            }
        }
        __syncthreads();
        // descending block scan over bins
        int nbins = (level == 3) ? 256 : 4096;
        int per = (nbins >= 1024) ? (nbins >> 10) : 1;
        int hi = nbins - 1 - t*per;
        unsigned c = 0; float q = 0.f;
        if (hi >= 0){
            for (int i=0;i<per;i++){ int bx = hi - i; if (bx >= 0){ c += hC[bx]; q += hQ[bx]; } }
        }
        scC[t] = c; scQ[t] = q;
        __syncthreads();
        for (int off=1; off<1024; off<<=1){
            unsigned cv = (t >= off) ? scC[t-off] : 0u;
            float    qv = (t >= off) ? scQ[t-off] : 0.f;
            __syncthreads();
            scC[t] += cv; scQ[t] += qv;
            __syncthreads();
        }
        unsigned incl = scC[t], excl = incl - c;
        if (hi >= 0 && (int)excl < K && K <= (int)incl){
            unsigned acc = excl;
            float qacc = scQ[t] - q;
            int chosen = hi;
            for (int i=0;i<per;i++){
                int bx = hi - i;
                unsigned cc = hC[bx];
                if (acc + cc >= (unsigned)K){ chosen = bx; break; }
                acc += cc; qacc += hQ[bx];
            }
            sK = K - (int)acc;
            sNegsel += qacc;
            if (level == 1)      sPrefix = ((unsigned)chosen) << 20;
            else if (level == 2) sPrefix |= ((unsigned)chosen) << 8;
            else                 sPrefix |= (unsigned)chosen;
        }
        __syncthreads();
    }
    if (t == 0){
        float tv = __uint_as_float(sPrefix);
        g_negselSum[b] = sNegsel + (float)sK * tv * tv;   // leaf ties: exact value
    }
}

// ---------------- kernels dice: all 5 channels per batch, float4 -----------
// grid (96, Bn) x 256
__global__ void k_kern(const float* __restrict__ pred,
                       const float* __restrict__ gtk,
                       const float* __restrict__ tm){
    int b = blockIdx.y;
    const float4* mm4 = (const float4*)(tm + b*HW);
    float si[5], s1[5], s2[5];
    #pragma unroll
    for (int kc=0;kc<5;kc++){ si[kc]=0.f; s1[kc]=0.f; s2[kc]=0.f; }
    int stride = gridDim.x*blockDim.x;
    for (int i = blockIdx.x*blockDim.x + threadIdx.x; i < HW4; i += stride){
        float4 m = mm4[i];
        #pragma unroll
        for (int kc=0;kc<5;kc++){
            float4 p = ((const float4*)(pred + (b*NCH + 1 + kc)*HW))[i];
            float4 g = ((const float4*)(gtk  + (b*NKER + kc)*HW))[i];
            if (m.x > 0.5f){ float pp = sigm(p.x); si[kc]+=pp*g.x; s1[kc]+=pp*pp; s2[kc]+=g.x; }
            if (m.y > 0.5f){ float pp = sigm(p.y); si[kc]+=pp*g.y; s1[kc]+=pp*pp; s2[kc]+=g.y; }
            if (m.z > 0.5f){ float pp = sigm(p.z); si[kc]+=pp*g.z; s1[kc]+=pp*pp; s2[kc]+=g.z; }
            if (m.w > 0.5f){ float pp = sigm(p.w); si[kc]+=pp*g.w; s1[kc]+=pp*pp; s2[kc]+=g.w; }
        }
    }
    int lane = threadIdx.x & 31;
    #pragma unroll
    for (int kc=0;kc<5;kc++){
        float a = si[kc], u = s1[kc], c = s2[kc];
        #pragma unroll
        for (int o=16;o;o>>=1){
            a += __shfl_down_sync(0xffffffffu, a, o);
            u += __shfl_down_sync(0xffffffffu, u, o);
            c += __shfl_down_sync(0xffffffffu, c, o);
        }
        if (lane == 0){
            atomicAdd(&g_kInter[b*NKER+kc], a);
            atomicAdd(&g_kU1[b*NKER+kc], u);
            atomicAdd(&g_kU2[b*NKER+kc], c);
        }
    }
}

// ---------------- emb pass 1: per-label counts + sums ----------------------
// grid (96, Bn) x 256; per-half-warp tables (16 tables)
__global__ void k_emb1(const float* __restrict__ pred,
                       const int* __restrict__ inst,
                       const float* __restrict__ tm){
    __shared__ float sA[16][NL*5];     // sub-table per half-warp
    int b = blockIdx.y;
    int sub = threadIdx.x >> 4;
    for (int i = threadIdx.x; i < 16*NL*5; i += 256) ((float*)sA)[i] = 0.f;
    __syncthreads();
    const float4* tm4 = (const float4*)(tm + b*HW);
    const int4*   in4 = (const int4*)(inst + b*HW);
    const float4* e0 = (const float4*)(pred + (b*NCH + 6)*HW);
    const float4* e1 = (const float4*)(pred + (b*NCH + 7)*HW);
    const float4* e2 = (const float4*)(pred + (b*NCH + 8)*HW);
    const float4* e3 = (const float4*)(pred + (b*NCH + 9)*HW);
    int stride = gridDim.x*blockDim.x;
    for (int i = blockIdx.x*blockDim.x + threadIdx.x; i < HW4; i += stride){
        float4 m = tm4[i]; int4 gi = in4[i];
        float4 a = e0[i], bb = e1[i], c = e2[i], d = e3[i];
        if (m.x > 0.5f){ float* p = &sA[sub][(gi.x & 15)*5];
            atomicAdd(p,1.f); atomicAdd(p+1,a.x); atomicAdd(p+2,bb.x); atomicAdd(p+3,c.x); atomicAdd(p+4,d.x); }
        if (m.y > 0.5f){ float* p = &sA[sub][(gi.y & 15)*5];
            atomicAdd(p,1.f); atomicAdd(p+1,a.y); atomicAdd(p+2,bb.y); atomicAdd(p+3,c.y); atomicAdd(p+4,d.y); }
        if (m.z > 0.5f){ float* p = &sA[sub][(gi.z & 15)*5];
            atomicAdd(p,1.f); atomicAdd(p+1,a.z); atomicAdd(p+2,bb.z); atomicAdd(p+3,c.z); atomicAdd(p+4,d.z); }
        if (m.w > 0.5f){ float* p = &sA[sub][(gi.w & 15)*5];
            atomicAdd(p,1.f); atomicAdd(p+1,a.w); atomicAdd(p+2,bb.w); atomicAdd(p+3,c.w); atomicAdd(p+4,d.w); }
    }
    __syncthreads();
    for (int i = threadIdx.x; i < NL*5; i += 256){
        int l = i/5, comp = i - 5*l;
        float s = 0.f;
        #pragma unroll
        for (int w=0; w<16; w++) s += sA[w][l*5+comp];
        if (s != 0.f){
            if (comp == 0) atomicAdd(&g_embCnt[b][l], s);
            else           atomicAdd(&g_embSum[b][l][comp-1], s);
        }
    }
}

// ---------------- emb pass 2: hinge variance, weighted scalar accum --------
// grid (96, Bn) x 256 — no label atomics at all
__global__ void k_emb2(const float* __restrict__ pred,
                       const int* __restrict__ inst,
                       const float* __restrict__ tm){
    __shared__ float sM[NL][4];
    __shared__ float sInv[NL];
    __shared__ float sRed[8];
    int b = blockIdx.y;
    if (threadIdx.x < NL){
        int l = threadIdx.x;
        float c = g_embCnt[b][l];
        float inv = 1.f / fmaxf(c, 1.f);
        sInv[l] = inv;
        #pragma unroll
        for (int d=0;d<4;d++) sM[l][d] = g_embSum[b][l][d]*inv;
    }
    __syncthreads();
    const float4* tm4 = (const float4*)(tm + b*HW);
    const int4*   in4 = (const int4*)(inst + b*HW);
    const float4* e0 = (const float4*)(pred + (b*NCH + 6)*HW);
    const float4* e1 = (const float4*)(pred + (b*NCH + 7)*HW);
    const float4* e2 = (const float4*)(pred + (b*NCH + 8)*HW);
    const float4* e3 = (const float4*)(pred + (b*NCH + 9)*HW);
    int stride = gridDim.x*blockDim.x;
    float acc = 0.f;
    for (int i = blockIdx.x*blockDim.x + threadIdx.x; i < HW4; i += stride){
        float4 m = tm4[i]; int4 gi = in4[i];
        float4 a = e0[i], bb = e1[i], c = e2[i], d = e3[i];
        float mv[4] = {m.x, m.y, m.z, m.w};
        int   lv[4] = {gi.x & 15, gi.y & 15, gi.z & 15, gi.w & 15};
        float av[4] = {a.x, a.y, a.z, a.w};
        float bv[4] = {bb.x, bb.y, bb.z, bb.w};
        float cv[4] = {c.x, c.y, c.z, c.w};
        float dv[4] = {d.x, d.y, d.z, d.w};
        #pragma unroll
        for (int comp=0; comp<4; comp++){
            if (mv[comp] > 0.5f){
                int l = lv[comp];
                float v0 = av[comp] - sM[l][0];
                float v1 = bv[comp] - sM[l][1];
                float v2 = cv[comp] - sM[l][2];
                float v3 = dv[comp] - sM[l][3];
                float dd = sqrtf(v0*v0+v1*v1+v2*v2+v3*v3 + 1e-12f);
                float h = dd - 0.5f;
                if (h > 0.f) acc += h*h*sInv[l];
            }
        }
    }
    int lane = threadIdx.x & 31, wid = threadIdx.x >> 5;
    #pragma unroll
    for (int o=16;o;o>>=1) acc += __shfl_down_sync(0xffffffffu, acc, o);
    if (lane == 0) sRed[wid] = acc;
    __syncthreads();
    if (threadIdx.x == 0){
        float s = 0.f;
        #pragma unroll
        for (int w=0;w<8;w++) s += sRed[w];
        if (s != 0.f) atomicAdd(&g_lvSum[b], s);
    }
}

// ---------------- final assembly -------------------------------------------
__global__ void k_final(float* out){
    if (threadIdx.x != 0 || blockIdx.x != 0) return;
    float loss_text = 0.f;
    for (int b=0;b<Bn;b++){
        float inter = g_posSum[b];
        float uni = g_posSum2[b] + g_negselSum[b] + (float)g_npos[b] + 1e-6f;
        loss_text += 1.f - 2.f*inter/uni;
    }
    loss_text /= (float)Bn;
    float loss_k = 0.f;
    for (int r=0;r<Bn*NKER;r++){
        float uni = g_kU1[r] + g_kU2[r] + 1e-6f;
        loss_k += 1.f - 2.f*g_kInter[r]/uni;
    }
    loss_k /= (float)(Bn*NKER);
    float lvT=0.f, ldT=0.f, lrT=0.f;
    for (int b=0;b<Bn;b++){
        int n=0;
        bool pres[NL];
        float mean[NL][4];
        for (int l=0;l<NL;l++){
            float c = g_embCnt[b][l];
            pres[l] = c > 0.f;
            if (pres[l]) n++;
            float inv = 1.f/fmaxf(c,1.f);
            for (int d=0;d<4;d++) mean[l][d] = g_embSum[b][l][d]*inv;
        }
        float nf = (float)n;
        float lv = g_lvSum[b] / fmaxf(nf, 1.f);
        float ld = 0.f;
        for (int i=0;i<NL;i++) for (int j=i+1;j<NL;j++){
            if (pres[i] && pres[j]){
                float d2=0.f;
                for (int d=0;d<4;d++){
                    float df = mean[i][d]-mean[j][d];
                    d2 += df*df;
                }
                float pd = sqrtf(d2 + 1e-12f);
                float h = fmaxf(3.0f - pd, 0.f);
                ld += h*h;
            }
        }
        ld /= fmaxf(nf*(nf-1.f), 1.f);
        float lr = 0.f;
        for (int l=0;l<NL;l++){
            if (pres[l]){
                float d2=0.f;
                for (int d=0;d<4;d++) d2 += mean[l][d]*mean[l][d];
                lr += sqrtf(d2 + 1e-12f);
            }
        }
        lr /= fmaxf(nf, 1.f);
        float act = (n > 1) ? 1.f : 0.f;
        lvT += act*lv; ldT += act*ld; lrT += act*lr;
    }
    float loss_emb = 0.25f*(lvT + ldT + 0.001f*(lrT/(float)Bn));
    float loss = loss_k + 0.5f*loss_text + loss_emb;
    out[0]=loss; out[1]=loss_text; out[2]=loss_k; out[3]=loss_emb;
}

// ---------------- launch ---------------------------------------------------
extern "C" void kernel_launch(void* const* d_in, const int* in_sizes, int n_in,
                              void* d_out, int out_size){
    const float* pred   = (const float*)d_in[0];
    const float* gtText = (const float*)d_in[1];
    const float* gtk    = (const float*)d_in[2];
    const float* tm     = (const float*)d_in[3];
    const int*   inst   = (const int*)d_in[4];
    float* out = (float*)d_out;

    k_zero<<<1, 256>>>();
    k_dilstats<<<dim3(20,20,Bn), dim3(32,8)>>>(pred, gtText, tm);
    k_selectAll<<<Bn, 1024>>>();
    k_kern<<<dim3(96, Bn), 256>>>(pred, gtk, tm);
    k_emb1<<<dim3(96, Bn), 256>>>(pred, inst, tm);
    k_emb2<<<dim3(96, Bn), 256>>>(pred, inst, tm);
    k_final<<<1, 32>>>(out);
}

// round 5
// speedup vs baseline: 18.2518x; 18.2518x over previous
#include <cuda_runtime.h>
#include <math.h>

#define Bn 8
#define Hh 640
#define Ww 640
#define HW (Hh*Ww)          // 409600
#define HW4 (HW/4)          // 102400
#define NCH 10
#define NKER 5
#define NL 16
#define NEGINF (-1e30f)

// ---------------- scratch ----------------
__device__ unsigned g_negbits[Bn*HW];
__device__ int      g_negcount[Bn];
__device__ int      g_npos[Bn];
__device__ float    g_posSum[Bn], g_posSum2[Bn];
__device__ float    g_totNegQ[Bn];
__device__ float    g_negselSum[Bn];
__device__ float    g_kInter[Bn*NKER], g_kU1[Bn*NKER], g_kU2[Bn*NKER];
__device__ float    g_embCnt[Bn][NL];
__device__ float    g_embSum[Bn][NL][4];
__device__ float    g_lvSum[Bn];

__device__ __forceinline__ float sigm(float x){ return 1.0f/(1.0f+expf(-x)); }

// ---------------- zero ----------------
__global__ void k_zero(){
    int idx = threadIdx.x;
    if (idx < Bn){
        g_negcount[idx]=0; g_npos[idx]=0; g_posSum[idx]=0.f; g_posSum2[idx]=0.f;
        g_negselSum[idx]=0.f; g_lvSum[idx]=0.f; g_totNegQ[idx]=0.f;
    }
    if (idx < Bn*NKER){ g_kInter[idx]=0.f; g_kU1[idx]=0.f; g_kU2[idx]=0.f; }
    if (idx < Bn*NL) ((float*)g_embCnt)[idx]=0.f;
    for (int i = idx; i < Bn*NL*4; i += 256) ((float*)g_embSum)[i]=0.f;
}

// ------- fused dilate (sigmoid-of-max) + OHEM stats + staged compaction ----
// grid (20,20,Bn), block (32,8). Tile 32x32, halo 4.
__global__ void k_dilstats(const float* __restrict__ pred,
                           const float* __restrict__ gt,
                           const float* __restrict__ tm){
    __shared__ float sIn[40][41];
    __shared__ float sHm[40][33];
    __shared__ unsigned sNeg[1024];
    __shared__ int sCnt, sBase;
    __shared__ float sR0[8], sR1[8], sR2[8], sR3[8];
    int b = blockIdx.z;
    int gx0 = blockIdx.x*32 - 4, gy0 = blockIdx.y*32 - 4;
    int tid = threadIdx.y*32 + threadIdx.x;
    int lane = tid & 31, wid = tid >> 5;
    const float* p0 = pred + b*NCH*HW;

    if (tid == 0) sCnt = 0;
    for (int idx = tid; idx < 1600; idx += 256){
        int r = idx/40, c = idx - 40*r;
        int gy = gy0 + r, gx = gx0 + c;
        sIn[r][c] = (gy>=0 && gy<Hh && gx>=0 && gx<Ww) ? p0[gy*Ww + gx] : NEGINF;
    }
    __syncthreads();
    for (int idx = tid; idx < 1280; idx += 256){
        int r = idx >> 5, c = idx & 31;
        float m = sIn[r][c];
        #pragma unroll
        for (int j=1;j<9;j++) m = fmaxf(m, sIn[r][c+j]);
        sHm[r][c] = m;
    }
    __syncthreads();

    int pc = 0; float ps = 0.f, ps2 = 0.f, qn = 0.f;
    #pragma unroll
    for (int k=0;k<4;k++){
        int r = threadIdx.y*4 + k;
        int c = threadIdx.x;
        float m = sHm[r][c];
        #pragma unroll
        for (int j=1;j<9;j++) m = fmaxf(m, sHm[r+j][c]);
        float v = sigm(m);                  // sigmoid after max (monotone)
        int gy = gy0 + 4 + r, gx = gx0 + 4 + c;
        int gi = b*HW + gy*Ww + gx;
        float g  = gt[gi];
        float mm = tm[gi];
        bool isPos = (g > 0.5f) && (mm > 0.5f);
        bool isNeg = (g <= 0.5f) && (mm > 0.5f);
        if (isPos){ pc++; ps += v; ps2 += v*v; }
        if (isNeg) qn += v*v;
        unsigned ball = __ballot_sync(0xffffffffu, isNeg);
        if (isNeg){
            int rank = __popc(ball & ((1u<<lane)-1u));
            int leader = __ffs(ball)-1;
            int base = 0;
            if (lane == leader) base = atomicAdd(&sCnt, __popc(ball));
            base = __shfl_sync(ball, base, leader);
            sNeg[base + rank] = __float_as_uint(v);
        }
    }
    // warp reduce stats
    #pragma unroll
    for (int o=16;o;o>>=1){
        pc  += __shfl_down_sync(0xffffffffu, pc, o);
        ps  += __shfl_down_sync(0xffffffffu, ps, o);
        ps2 += __shfl_down_sync(0xffffffffu, ps2, o);
        qn  += __shfl_down_sync(0xffffffffu, qn, o);
    }
    if (lane == 0){ sR0[wid]=(float)pc; sR1[wid]=ps; sR2[wid]=ps2; sR3[wid]=qn; }
    __syncthreads();        // covers sNeg, sCnt, sR*
    if (tid == 0){
        float a=0,bb=0,cc=0,dd=0;
        #pragma unroll
        for (int w=0;w<8;w++){ a+=sR0[w]; bb+=sR1[w]; cc+=sR2[w]; dd+=sR3[w]; }
        if (a  != 0.f) atomicAdd(&g_npos[b], (int)a);
        if (bb != 0.f) atomicAdd(&g_posSum[b], bb);
        if (cc != 0.f) atomicAdd(&g_posSum2[b], cc);
        if (dd != 0.f) atomicAdd(&g_totNegQ[b], dd);
        sBase = atomicAdd(&g_negcount[b], sCnt);
    }
    __syncthreads();
    int cnt = sCnt, base = sBase;
    unsigned* dst = g_negbits + b*HW + base;
    for (int i = tid; i < cnt; i += 256) dst[i] = sNeg[i];
}

// ---------- radix select fallback (null launch when k >= cnt) --------------
// grid Bn x 1024
__global__ void k_selectAll(){
    __shared__ unsigned hC[4096];
    __shared__ float    hQ[4096];
    __shared__ unsigned scC[1024];
    __shared__ float    scQ[1024];
    __shared__ unsigned sPrefix;
    __shared__ int      sK;
    __shared__ float    sNegsel;
    int b = blockIdx.x;
    int t = threadIdx.x;
    int cnt = g_negcount[b];
    int k0 = 3*g_npos[b]; if (k0 > cnt) k0 = cnt;
    if (k0 >= cnt){                       // common path: all negatives selected
        if (t == 0) g_negselSum[b] = g_totNegQ[b];
        return;
    }
    if (k0 <= 0){
        if (t == 0) g_negselSum[b] = 0.f;
        return;
    }
    if (t == 0){ sK = k0; sNegsel = 0.f; sPrefix = 0u; }
    __syncthreads();
    const unsigned* nb = g_negbits + b*HW;
    for (int level = 1; level <= 3; level++){
        int K = sK;
        unsigned pfx = sPrefix;
        for (int i=t;i<4096;i+=1024){ hC[i]=0u; hQ[i]=0.f; }
        __syncthreads();
        for (int j = t; j - t < cnt; j += 1024){
            bool in = j < cnt;
            unsigned bits = in ? nb[j] : 0u;
            unsigned bin = 0; bool ok = false;
            if (in){
                if (level == 1){ bin = bits >> 20; ok = true; }
                else if (level == 2){ ok = (bits>>20)==(pfx>>20); bin = (bits>>8)&0xFFFu; }
                else { ok = (bits>>8)==(pfx>>8); bin = bits & 0xFFu; }
            }
            float v = __uint_as_float(bits);
            float q = v*v;
            unsigned key = ok ? bin : 0xFFFFFFFFu;
            unsigned grp = __match_any_sync(0xffffffffu, key);
            if (grp == 0xffffffffu){
                if (ok){
                    #pragma unroll
                    for (int o=16;o;o>>=1) q += __shfl_down_sync(0xffffffffu, q, o);
                    if ((t & 31) == 0){ atomicAdd(&hC[bin], 32u); atomicAdd(&hQ[bin], q); }
                }
            } else if (ok){
                atomicAdd(&hC[bin], 1u); atomicAdd(&hQ[bin], q);
            }
        }
        __syncthreads();
        int nbins = (level == 3) ? 256 : 4096;
        int per = (nbins >= 1024) ? (nbins >> 10) : 1;
        int hi = nbins - 1 - t*per;
        unsigned c = 0; float q = 0.f;
        if (hi >= 0){
            for (int i=0;i<per;i++){ int bx = hi - i; if (bx >= 0){ c += hC[bx]; q += hQ[bx]; } }
        }
        scC[t] = c; scQ[t] = q;
        __syncthreads();
        for (int off=1; off<1024; off<<=1){
            unsigned cv = (t >= off) ? scC[t-off] : 0u;
            float    qv = (t >= off) ? scQ[t-off] : 0.f;
            __syncthreads();
            scC[t] += cv; scQ[t] += qv;
            __syncthreads();
        }
        unsigned incl = scC[t], excl = incl - c;
        if (hi >= 0 && (int)excl < K && K <= (int)incl){
            unsigned acc = excl;
            float qacc = scQ[t] - q;
            int chosen = hi;
            for (int i=0;i<per;i++){
                int bx = hi - i;
                unsigned cc = hC[bx];
                if (acc + cc >= (unsigned)K){ chosen = bx; break; }
                acc += cc; qacc += hQ[bx];
            }
            sK = K - (int)acc;
            sNegsel += qacc;
            if (level == 1)      sPrefix = ((unsigned)chosen) << 20;
            else if (level == 2) sPrefix |= ((unsigned)chosen) << 8;
            else                 sPrefix |= (unsigned)chosen;
        }
        __syncthreads();
    }
    if (t == 0){
        float tv = __uint_as_float(sPrefix);
        g_negselSum[b] = sNegsel + (float)sK * tv * tv;
    }
}

// ---------------- kernels dice: flat grid, 1 quad/thread -------------------
// grid 3200 x 256 ; 400 blocks per batch (HW4 = 400*256)
__global__ void k_kern(const float* __restrict__ pred,
                       const float* __restrict__ gtk,
                       const float* __restrict__ tm){
    __shared__ float sRed[8][15];
    int b = blockIdx.x / 400;
    int i = (blockIdx.x - b*400)*256 + threadIdx.x;
    float4 m = ((const float4*)(tm + b*HW))[i];
    const float* pb = pred + (b*NCH + 1)*HW;
    const float* gb = gtk  + b*NKER*HW;
    float si[5], s1[5], s2[5];
    #pragma unroll
    for (int kc=0;kc<5;kc++){
        float4 p = ((const float4*)(pb + kc*HW))[i];
        float4 g = ((const float4*)(gb + kc*HW))[i];
        float a=0.f,u=0.f,c=0.f;
        if (m.x > 0.5f){ float pp = sigm(p.x); a+=pp*g.x; u+=pp*pp; c+=g.x; }
        if (m.y > 0.5f){ float pp = sigm(p.y); a+=pp*g.y; u+=pp*pp; c+=g.y; }
        if (m.z > 0.5f){ float pp = sigm(p.z); a+=pp*g.z; u+=pp*pp; c+=g.z; }
        if (m.w > 0.5f){ float pp = sigm(p.w); a+=pp*g.w; u+=pp*pp; c+=g.w; }
        si[kc]=a; s1[kc]=u; s2[kc]=c;
    }
    int lane = threadIdx.x & 31, wid = threadIdx.x >> 5;
    #pragma unroll
    for (int kc=0;kc<5;kc++){
        float a = si[kc], u = s1[kc], c = s2[kc];
        #pragma unroll
        for (int o=16;o;o>>=1){
            a += __shfl_down_sync(0xffffffffu, a, o);
            u += __shfl_down_sync(0xffffffffu, u, o);
            c += __shfl_down_sync(0xffffffffu, c, o);
        }
        if (lane == 0){ sRed[wid][kc*3]=a; sRed[wid][kc*3+1]=u; sRed[wid][kc*3+2]=c; }
    }
    __syncthreads();
    if (threadIdx.x < 15){
        float s = 0.f;
        #pragma unroll
        for (int w=0;w<8;w++) s += sRed[w][threadIdx.x];
        int kc = threadIdx.x/3, comp = threadIdx.x - 3*kc;
        if (s != 0.f){
            if (comp==0) atomicAdd(&g_kInter[b*NKER+kc], s);
            else if (comp==1) atomicAdd(&g_kU1[b*NKER+kc], s);
            else atomicAdd(&g_kU2[b*NKER+kc], s);
        }
    }
}

// ---------------- emb pass 1: private per-thread smem tables ---------------
// grid (96, Bn) x 128 ; zero atomics
__global__ void __launch_bounds__(128) k_emb1(const float* __restrict__ pred,
                       const int* __restrict__ inst,
                       const float* __restrict__ tm){
    __shared__ float sT[128][81];      // stride 81: bank-spread
    int b = blockIdx.y;
    int t = threadIdx.x;
    #pragma unroll
    for (int j=0;j<81;j++) sT[t][j] = 0.f;
    __syncthreads();
    const float4* tm4 = (const float4*)(tm + b*HW);
    const int4*   in4 = (const int4*)(inst + b*HW);
    const float4* e0 = (const float4*)(pred + (b*NCH + 6)*HW);
    const float4* e1 = (const float4*)(pred + (b*NCH + 7)*HW);
    const float4* e2 = (const float4*)(pred + (b*NCH + 8)*HW);
    const float4* e3 = (const float4*)(pred + (b*NCH + 9)*HW);
    int stride = gridDim.x*blockDim.x;
    float* T = sT[t];
    for (int i = blockIdx.x*blockDim.x + t; i < HW4; i += stride){
        float4 m = tm4[i]; int4 gi = in4[i];
        float4 a = e0[i], bb = e1[i], c = e2[i], d = e3[i];
        if (m.x > 0.5f){ float* p = T + (gi.x & 15)*5;
            p[0]+=1.f; p[1]+=a.x; p[2]+=bb.x; p[3]+=c.x; p[4]+=d.x; }
        if (m.y > 0.5f){ float* p = T + (gi.y & 15)*5;
            p[0]+=1.f; p[1]+=a.y; p[2]+=bb.y; p[3]+=c.y; p[4]+=d.y; }
        if (m.z > 0.5f){ float* p = T + (gi.z & 15)*5;
            p[0]+=1.f; p[1]+=a.z; p[2]+=bb.z; p[3]+=c.z; p[4]+=d.z; }
        if (m.w > 0.5f){ float* p = T + (gi.w & 15)*5;
            p[0]+=1.f; p[1]+=a.w; p[2]+=bb.w; p[3]+=c.w; p[4]+=d.w; }
    }
    __syncthreads();
    if (t < 80){
        float s = 0.f;
        #pragma unroll 8
        for (int r=0;r<128;r++) s += sT[r][t];
        if (s != 0.f){
            int l = t/5, comp = t - 5*l;
            if (comp == 0) atomicAdd(&g_embCnt[b][l], s);
            else           atomicAdd(&g_embSum[b][l][comp-1], s);
        }
    }
}

// ---------------- emb pass 2: hinge variance, flat grid, 1 quad/thread -----
// grid 3200 x 256
__global__ void k_emb2(const float* __restrict__ pred,
                       const int* __restrict__ inst,
                       const float* __restrict__ tm){
    __shared__ float sM[NL][4];
    __shared__ float sInv[NL];
    __shared__ float sRed[8];
    int b = blockIdx.x / 400;
    int i = (blockIdx.x - b*400)*256 + threadIdx.x;
    if (threadIdx.x < NL){
        int l = threadIdx.x;
        float c = g_embCnt[b][l];
        float inv = 1.f / fmaxf(c, 1.f);
        sInv[l] = inv;
        #pragma unroll
        for (int d=0;d<4;d++) sM[l][d] = g_embSum[b][l][d]*inv;
    }
    __syncthreads();
    float4 m = ((const float4*)(tm + b*HW))[i];
    int4 gi  = ((const int4*)(inst + b*HW))[i];
    float4 a = ((const float4*)(pred + (b*NCH + 6)*HW))[i];
    float4 bb= ((const float4*)(pred + (b*NCH + 7)*HW))[i];
    float4 c = ((const float4*)(pred + (b*NCH + 8)*HW))[i];
    float4 d = ((const float4*)(pred + (b*NCH + 9)*HW))[i];
    float acc = 0.f;
    float mv[4] = {m.x, m.y, m.z, m.w};
    int   lv[4] = {gi.x & 15, gi.y & 15, gi.z & 15, gi.w & 15};
    float av[4] = {a.x, a.y, a.z, a.w};
    float bv[4] = {bb.x, bb.y, bb.z, bb.w};
    float cv[4] = {c.x, c.y, c.z, c.w};
    float dv[4] = {d.x, d.y, d.z, d.w};
    #pragma unroll
    for (int comp=0; comp<4; comp++){
        if (mv[comp] > 0.5f){
            int l = lv[comp];
            float v0 = av[comp] - sM[l][0];
            float v1 = bv[comp] - sM[l][1];
            float v2 = cv[comp] - sM[l][2];
            float v3 = dv[comp] - sM[l][3];
            float dd = sqrtf(v0*v0+v1*v1+v2*v2+v3*v3 + 1e-12f);
            float h = dd - 0.5f;
            if (h > 0.f) acc += h*h*sInv[l];
        }
    }
    int lane = threadIdx.x & 31, wid = threadIdx.x >> 5;
    #pragma unroll
    for (int o=16;o;o>>=1) acc += __shfl_down_sync(0xffffffffu, acc, o);
    if (lane == 0) sRed[wid] = acc;
    __syncthreads();
    if (threadIdx.x == 0){
        float s = 0.f;
        #pragma unroll
        for (int w=0;w<8;w++) s += sRed[w];
        if (s != 0.f) atomicAdd(&g_lvSum[b], s);
    }
}

// ---------------- final assembly -------------------------------------------
__global__ void k_final(float* out){
    if (threadIdx.x != 0 || blockIdx.x != 0) return;
    float loss_text = 0.f;
    for (int b=0;b<Bn;b++){
        float inter = g_posSum[b];
        float uni = g_posSum2[b] + g_negselSum[b] + (float)g_npos[b] + 1e-6f;
        loss_text += 1.f - 2.f*inter/uni;
    }
    loss_text /= (float)Bn;
    float loss_k = 0.f;
    for (int r=0;r<Bn*NKER;r++){
        float uni = g_kU1[r] + g_kU2[r] + 1e-6f;
        loss_k += 1.f - 2.f*g_kInter[r]/uni;
    }
    loss_k /= (float)(Bn*NKER);
    float lvT=0.f, ldT=0.f, lrT=0.f;
    for (int b=0;b<Bn;b++){
        int n=0;
        bool pres[NL];
        float mean[NL][4];
        for (int l=0;l<NL;l++){
            float cc = g_embCnt[b][l];
            pres[l] = cc > 0.f;
            if (pres[l]) n++;
            float inv = 1.f/fmaxf(cc,1.f);
            for (int d=0;d<4;d++) mean[l][d] = g_embSum[b][l][d]*inv;
        }
        float nf = (float)n;
        float lv = g_lvSum[b] / fmaxf(nf, 1.f);
        float ld = 0.f;
        for (int ii=0;ii<NL;ii++) for (int j=ii+1;j<NL;j++){
            if (pres[ii] && pres[j]){
                float d2=0.f;
                for (int d=0;d<4;d++){
                    float df = mean[ii][d]-mean[j][d];
                    d2 += df*df;
                }
                float pd = sqrtf(d2 + 1e-12f);
                float h = fmaxf(3.0f - pd, 0.f);
                ld += h*h;
            }
        }
        ld /= fmaxf(nf*(nf-1.f), 1.f);
        float lr = 0.f;
        for (int l=0;l<NL;l++){
            if (pres[l]){
                float d2=0.f;
                for (int d=0;d<4;d++) d2 += mean[l][d]*mean[l][d];
                lr += sqrtf(d2 + 1e-12f);
            }
        }
        lr /= fmaxf(nf, 1.f);
        float act = (n > 1) ? 1.f : 0.f;
        lvT += act*lv; ldT += act*ld; lrT += act*lr;
    }
    float loss_emb = 0.25f*(lvT + ldT + 0.001f*(lrT/(float)Bn));
    float loss = loss_k + 0.5f*loss_text + loss_emb;
    out[0]=loss; out[1]=loss_text; out[2]=loss_k; out[3]=loss_emb;
}

// ---------------- launch ---------------------------------------------------
extern "C" void kernel_launch(void* const* d_in, const int* in_sizes, int n_in,
                              void* d_out, int out_size){
    const float* pred   = (const float*)d_in[0];
    const float* gtText = (const float*)d_in[1];
    const float* gtk    = (const float*)d_in[2];
    const float* tm     = (const float*)d_in[3];
    const int*   inst   = (const int*)d_in[4];
    float* out = (float*)d_out;

    k_zero<<<1, 256>>>();
    k_dilstats<<<dim3(20,20,Bn), dim3(32,8)>>>(pred, gtText, tm);
    k_selectAll<<<Bn, 1024>>>();
    k_kern<<<3200, 256>>>(pred, gtk, tm);
    k_emb1<<<dim3(96, Bn), 128>>>(pred, inst, tm);
    k_emb2<<<3200, 256>>>(pred, inst, tm);
    k_final<<<1, 32>>>(out);
}

// round 7
// speedup vs baseline: 19.8154x; 1.0857x over previous
#include <cuda_runtime.h>
#include <math.h>

#define Bn 8
#define Hh 640
#define Ww 640
#define HW (Hh*Ww)          // 409600
#define HW4 (HW/4)          // 102400
#define NCH 10
#define NKER 5
#define NL 16
#define NEGINF (-1e30f)

// ---------------- scratch ----------------
struct Scal {
    int   negcount[Bn];
    int   npos[Bn];
    float posSum[Bn], posSum2[Bn], totNegQ[Bn], negselSum[Bn], lvSum[Bn];
    float kInter[Bn*NKER], kU1[Bn*NKER], kU2[Bn*NKER];
    float embCnt[Bn][NL];
    float embSum[Bn][NL][4];
};
__device__ Scal gS;
__device__ unsigned g_negbits[Bn*HW];

__device__ __forceinline__ float sigm(float x){ return 1.0f/(1.0f+expf(-x)); }

// ------- fused dilate (sigmoid-of-max) + OHEM stats + staged compaction ----
// grid (20,20,Bn), block (32,8). Tile 32x32, halo 4.
__global__ void k_dilstats(const float* __restrict__ pred,
                           const float* __restrict__ gt,
                           const float* __restrict__ tm){
    __shared__ float sIn[40][41];
    __shared__ float sHm[40][33];
    __shared__ unsigned sNeg[1024];
    __shared__ int sCnt, sBase;
    __shared__ float sR0[8], sR1[8], sR2[8], sR3[8];
    int b = blockIdx.z;
    int gx0 = blockIdx.x*32 - 4, gy0 = blockIdx.y*32 - 4;
    int tid = threadIdx.y*32 + threadIdx.x;
    int lane = tid & 31, wid = tid >> 5;
    const float* p0 = pred + b*NCH*HW;

    if (tid == 0) sCnt = 0;
    for (int idx = tid; idx < 1600; idx += 256){
        int r = idx/40, c = idx - 40*r;
        int gy = gy0 + r, gx = gx0 + c;
        sIn[r][c] = (gy>=0 && gy<Hh && gx>=0 && gx<Ww) ? p0[gy*Ww + gx] : NEGINF;
    }
    __syncthreads();
    for (int idx = tid; idx < 1280; idx += 256){
        int r = idx >> 5, c = idx & 31;
        float m = sIn[r][c];
        #pragma unroll
        for (int j=1;j<9;j++) m = fmaxf(m, sIn[r][c+j]);
        sHm[r][c] = m;
    }
    __syncthreads();

    int pc = 0; float ps = 0.f, ps2 = 0.f, qn = 0.f;
    #pragma unroll
    for (int k=0;k<4;k++){
        int r = threadIdx.y*4 + k;
        int c = threadIdx.x;
        float m = sHm[r][c];
        #pragma unroll
        for (int j=1;j<9;j++) m = fmaxf(m, sHm[r+j][c]);
        float v = sigm(m);                  // sigmoid after max (monotone)
        int gy = gy0 + 4 + r, gx = gx0 + 4 + c;
        int gi = b*HW + gy*Ww + gx;
        float g  = gt[gi];
        float mm = tm[gi];
        bool isPos = (g > 0.5f) && (mm > 0.5f);
        bool isNeg = (g <= 0.5f) && (mm > 0.5f);
        if (isPos){ pc++; ps += v; ps2 += v*v; }
        if (isNeg) qn += v*v;
        unsigned ball = __ballot_sync(0xffffffffu, isNeg);
        if (isNeg){
            int rank = __popc(ball & ((1u<<lane)-1u));
            int leader = __ffs(ball)-1;
            int base = 0;
            if (lane == leader) base = atomicAdd(&sCnt, __popc(ball));
            base = __shfl_sync(ball, base, leader);
            sNeg[base + rank] = __float_as_uint(v);
        }
    }
    #pragma unroll
    for (int o=16;o;o>>=1){
        pc  += __shfl_down_sync(0xffffffffu, pc, o);
        ps  += __shfl_down_sync(0xffffffffu, ps, o);
        ps2 += __shfl_down_sync(0xffffffffu, ps2, o);
        qn  += __shfl_down_sync(0xffffffffu, qn, o);
    }
    if (lane == 0){ sR0[wid]=(float)pc; sR1[wid]=ps; sR2[wid]=ps2; sR3[wid]=qn; }
    __syncthreads();        // covers sNeg, sCnt, sR*
    if (tid == 0){
        float a=0,bb=0,cc=0,dd=0;
        #pragma unroll
        for (int w=0;w<8;w++){ a+=sR0[w]; bb+=sR1[w]; cc+=sR2[w]; dd+=sR3[w]; }
        if (a  != 0.f) atomicAdd(&gS.npos[b], (int)a);
        if (bb != 0.f) atomicAdd(&gS.posSum[b], bb);
        if (cc != 0.f) atomicAdd(&gS.posSum2[b], cc);
        if (dd != 0.f) atomicAdd(&gS.totNegQ[b], dd);
        sBase = atomicAdd(&gS.negcount[b], sCnt);
    }
    __syncthreads();
    int cnt = sCnt, base = sBase;
    unsigned* dst = g_negbits + b*HW + base;
    for (int i = tid; i < cnt; i += 256) dst[i] = sNeg[i];
}

// ---------- radix select fallback (null launch when k >= cnt) --------------
// grid Bn x 1024
__global__ void k_selectAll(){
    __shared__ unsigned hC[4096];
    __shared__ float    hQ[4096];
    __shared__ unsigned scC[1024];
    __shared__ float    scQ[1024];
    __shared__ unsigned sPrefix;
    __shared__ int      sK;
    __shared__ float    sNegsel;
    int b = blockIdx.x;
    int t = threadIdx.x;
    int cnt = gS.negcount[b];
    int k0 = 3*gS.npos[b]; if (k0 > cnt) k0 = cnt;
    if (k0 >= cnt){                       // common path: all negatives selected
        if (t == 0) gS.negselSum[b] = gS.totNegQ[b];
        return;
    }
    if (k0 <= 0){
        if (t == 0) gS.negselSum[b] = 0.f;
        return;
    }
    if (t == 0){ sK = k0; sNegsel = 0.f; sPrefix = 0u; }
    __syncthreads();
    const unsigned* nb = g_negbits + b*HW;
    for (int level = 1; level <= 3; level++){
        int K = sK;
        unsigned pfx = sPrefix;
        for (int i=t;i<4096;i+=1024){ hC[i]=0u; hQ[i]=0.f; }
        __syncthreads();
        for (int j = t; j - t < cnt; j += 1024){
            bool in = j < cnt;
            unsigned bits = in ? nb[j] : 0u;
            unsigned bin = 0; bool ok = false;
            if (in){
                if (level == 1){ bin = bits >> 20; ok = true; }
                else if (level == 2){ ok = (bits>>20)==(pfx>>20); bin = (bits>>8)&0xFFFu; }
                else { ok = (bits>>8)==(pfx>>8); bin = bits & 0xFFu; }
            }
            float v = __uint_as_float(bits);
            float q = v*v;
            unsigned key = ok ? bin : 0xFFFFFFFFu;
            unsigned grp = __match_any_sync(0xffffffffu, key);
            if (grp == 0xffffffffu){
                if (ok){
                    #pragma unroll
                    for (int o=16;o;o>>=1) q += __shfl_down_sync(0xffffffffu, q, o);
                    if ((t & 31) == 0){ atomicAdd(&hC[bin], 32u); atomicAdd(&hQ[bin], q); }
                }
            } else if (ok){
                atomicAdd(&hC[bin], 1u); atomicAdd(&hQ[bin], q);
            }
        }
        __syncthreads();
        int nbins = (level == 3) ? 256 : 4096;
        int per = (nbins >= 1024) ? (nbins >> 10) : 1;
        int hi = nbins - 1 - t*per;
        unsigned c = 0; float q = 0.f;
        if (hi >= 0){
            for (int i=0;i<per;i++){ int bx = hi - i; if (bx >= 0){ c += hC[bx]; q += hQ[bx]; } }
        }
        scC[t] = c; scQ[t] = q;
        __syncthreads();
        for (int off=1; off<1024; off<<=1){
            unsigned cv = (t >= off) ? scC[t-off] : 0u;
            float    qv = (t >= off) ? scQ[t-off] : 0.f;
            __syncthreads();
            scC[t] += cv; scQ[t] += qv;
            __syncthreads();
        }
        unsigned incl = scC[t], excl = incl - c;
        if (hi >= 0 && (int)excl < K && K <= (int)incl){
            unsigned acc = excl;
            float qacc = scQ[t] - q;
            int chosen = hi;
            for (int i=0;i<per;i++){
                int bx = hi - i;
                unsigned cc = hC[bx];
                if (acc + cc >= (unsigned)K){ chosen = bx; break; }
                acc += cc; qacc += hQ[bx];
            }
            sK = K - (int)acc;
            sNegsel += qacc;
            if (level == 1)      sPrefix = ((unsigned)chosen) << 20;
            else if (level == 2) sPrefix |= ((unsigned)chosen) << 8;
            else                 sPrefix |= (unsigned)chosen;
        }
        __syncthreads();
    }
    if (t == 0){
        float tv = __uint_as_float(sPrefix);
        gS.negselSum[b] = sNegsel + (float)sK * tv * tv;
    }
}

// ---------------- kernels dice: flat grid, 1 quad/thread -------------------
// grid 3200 x 256
__global__ void k_kern(const float* __restrict__ pred,
                       const float* __restrict__ gtk,
                       const float* __restrict__ tm){
    __shared__ float sRed[8][15];
    int b = blockIdx.x / 400;
    int i = (blockIdx.x - b*400)*256 + threadIdx.x;
    float4 m = ((const float4*)(tm + b*HW))[i];
    const float* pb = pred + (b*NCH + 1)*HW;
    const float* gb = gtk  + b*NKER*HW;
    float si[5], s1[5], s2[5];
    #pragma unroll
    for (int kc=0;kc<5;kc++){
        float4 p = ((const float4*)(pb + kc*HW))[i];
        float4 g = ((const float4*)(gb + kc*HW))[i];
        float a=0.f,u=0.f,c=0.f;
        if (m.x > 0.5f){ float pp = sigm(p.x); a+=pp*g.x; u+=pp*pp; c+=g.x; }
        if (m.y > 0.5f){ float pp = sigm(p.y); a+=pp*g.y; u+=pp*pp; c+=g.y; }
        if (m.z > 0.5f){ float pp = sigm(p.z); a+=pp*g.z; u+=pp*pp; c+=g.z; }
        if (m.w > 0.5f){ float pp = sigm(p.w); a+=pp*g.w; u+=pp*pp; c+=g.w; }
        si[kc]=a; s1[kc]=u; s2[kc]=c;
    }
    int lane = threadIdx.x & 31, wid = threadIdx.x >> 5;
    #pragma unroll
    for (int kc=0;kc<5;kc++){
        float a = si[kc], u = s1[kc], c = s2[kc];
        #pragma unroll
        for (int o=16;o;o>>=1){
            a += __shfl_down_sync(0xffffffffu, a, o);
            u += __shfl_down_sync(0xffffffffu, u, o);
            c += __shfl_down_sync(0xffffffffu, c, o);
        }
        if (lane == 0){ sRed[wid][kc*3]=a; sRed[wid][kc*3+1]=u; sRed[wid][kc*3+2]=c; }
    }
    __syncthreads();
    if (threadIdx.x < 15){
        float s = 0.f;
        #pragma unroll
        for (int w=0;w<8;w++) s += sRed[w][threadIdx.x];
        int kc = threadIdx.x/3, comp = threadIdx.x - 3*kc;
        if (s != 0.f){
            if (comp==0) atomicAdd(&gS.kInter[b*NKER+kc], s);
            else if (comp==1) atomicAdd(&gS.kU1[b*NKER+kc], s);
            else atomicAdd(&gS.kU2[b*NKER+kc], s);
        }
    }
}

// ---------------- emb pass 1: private per-thread smem tables ---------------
// grid (96, Bn) x 128 ; zero atomics in hot loop
__global__ void __launch_bounds__(128) k_emb1(const float* __restrict__ pred,
                       const int* __restrict__ inst,
                       const float* __restrict__ tm){
    __shared__ float sT[128][81];      // stride 81: bank-spread
    int b = blockIdx.y;
    int t = threadIdx.x;
    #pragma unroll
    for (int j=0;j<81;j++) sT[t][j] = 0.f;
    __syncthreads();
    const float4* tm4 = (const float4*)(tm + b*HW);
    const int4*   in4 = (const int4*)(inst + b*HW);
    const float4* e0 = (const float4*)(pred + (b*NCH + 6)*HW);
    const float4* e1 = (const float4*)(pred + (b*NCH + 7)*HW);
    const float4* e2 = (const float4*)(pred + (b*NCH + 8)*HW);
    const float4* e3 = (const float4*)(pred + (b*NCH + 9)*HW);
    int stride = gridDim.x*blockDim.x;
    float* T = sT[t];
    for (int i = blockIdx.x*blockDim.x + t; i < HW4; i += stride){
        float4 m = tm4[i]; int4 gi = in4[i];
        float4 a = e0[i], bb = e1[i], c = e2[i], d = e3[i];
        if (m.x > 0.5f){ float* p = T + (gi.x & 15)*5;
            p[0]+=1.f; p[1]+=a.x; p[2]+=bb.x; p[3]+=c.x; p[4]+=d.x; }
        if (m.y > 0.5f){ float* p = T + (gi.y & 15)*5;
            p[0]+=1.f; p[1]+=a.y; p[2]+=bb.y; p[3]+=c.y; p[4]+=d.y; }
        if (m.z > 0.5f){ float* p = T + (gi.z & 15)*5;
            p[0]+=1.f; p[1]+=a.z; p[2]+=bb.z; p[3]+=c.z; p[4]+=d.z; }
        if (m.w > 0.5f){ float* p = T + (gi.w & 15)*5;
            p[0]+=1.f; p[1]+=a.w; p[2]+=bb.w; p[3]+=c.w; p[4]+=d.w; }
    }
    __syncthreads();
    if (t < 80){
        float s = 0.f;
        #pragma unroll 8
        for (int r=0;r<128;r++) s += sT[r][t];
        if (s != 0.f){
            int l = t/5, comp = t - 5*l;
            if (comp == 0) atomicAdd(&gS.embCnt[b][l], s);
            else           atomicAdd(&gS.embSum[b][l][comp-1], s);
        }
    }
}

// ---------------- emb pass 2: hinge variance, flat grid, 1 quad/thread -----
// grid 3200 x 256
__global__ void k_emb2(const float* __restrict__ pred,
                       const int* __restrict__ inst,
                       const float* __restrict__ tm){
    __shared__ float sM[NL][4];
    __shared__ float sInv[NL];
    __shared__ float sRed[8];
    int b = blockIdx.x / 400;
    int i = (blockIdx.x - b*400)*256 + threadIdx.x;
    if (threadIdx.x < NL){
        int l = threadIdx.x;
        float c = gS.embCnt[b][l];
        float inv = 1.f / fmaxf(c, 1.f);
        sInv[l] = inv;
        #pragma unroll
        for (int d=0;d<4;d++) sM[l][d] = gS.embSum[b][l][d]*inv;
    }
    __syncthreads();
    float4 m = ((const float4*)(tm + b*HW))[i];
    int4 gi  = ((const int4*)(inst + b*HW))[i];
    float4 a = ((const float4*)(pred + (b*NCH + 6)*HW))[i];
    float4 bb= ((const float4*)(pred + (b*NCH + 7)*HW))[i];
    float4 c = ((const float4*)(pred + (b*NCH + 8)*HW))[i];
    float4 d = ((const float4*)(pred + (b*NCH + 9)*HW))[i];
    float acc = 0.f;
    float mv[4] = {m.x, m.y, m.z, m.w};
    int   lv[4] = {gi.x & 15, gi.y & 15, gi.z & 15, gi.w & 15};
    float av[4] = {a.x, a.y, a.z, a.w};
    float bv[4] = {bb.x, bb.y, bb.z, bb.w};
    float cv[4] = {c.x, c.y, c.z, c.w};
    float dv[4] = {d.x, d.y, d.z, d.w};
    #pragma unroll
    for (int comp=0; comp<4; comp++){
        if (mv[comp] > 0.5f){
            int l = lv[comp];
            float v0 = av[comp] - sM[l][0];
            float v1 = bv[comp] - sM[l][1];
            float v2 = cv[comp] - sM[l][2];
            float v3 = dv[comp] - sM[l][3];
            float dd = sqrtf(v0*v0+v1*v1+v2*v2+v3*v3 + 1e-12f);
            float h = dd - 0.5f;
            if (h > 0.f) acc += h*h*sInv[l];
        }
    }
    int lane = threadIdx.x & 31, wid = threadIdx.x >> 5;
    #pragma unroll
    for (int o=16;o;o>>=1) acc += __shfl_down_sync(0xffffffffu, acc, o);
    if (lane == 0) sRed[wid] = acc;
    __syncthreads();
    if (threadIdx.x == 0){
        float s = 0.f;
        #pragma unroll
        for (int w=0;w<8;w++) s += sRed[w];
        if (s != 0.f) atomicAdd(&gS.lvSum[b], s);
    }
}

// ---------------- final assembly -------------------------------------------
__global__ void k_final(float* out){
    if (threadIdx.x != 0 || blockIdx.x != 0) return;
    float loss_text = 0.f;
    for (int b=0;b<Bn;b++){
        float inter = gS.posSum[b];
        float uni = gS.posSum2[b] + gS.negselSum[b] + (float)gS.npos[b] + 1e-6f;
        loss_text += 1.f - 2.f*inter/uni;
    }
    loss_text /= (float)Bn;
    float loss_k = 0.f;
    for (int r=0;r<Bn*NKER;r++){
        float uni = gS.kU1[r] + gS.kU2[r] + 1e-6f;
        loss_k += 1.f - 2.f*gS.kInter[r]/uni;
    }
    loss_k /= (float)(Bn*NKER);
    float lvT=0.f, ldT=0.f, lrT=0.f;
    for (int b=0;b<Bn;b++){
        int n=0;
        bool pres[NL];
        float mean[NL][4];
        for (int l=0;l<NL;l++){
            float cc = gS.embCnt[b][l];
            pres[l] = cc > 0.f;
            if (pres[l]) n++;
            float inv = 1.f/fmaxf(cc,1.f);
            for (int d=0;d<4;d++) mean[l][d] = gS.embSum[b][l][d]*inv;
        }
        float nf = (float)n;
        float lv = gS.lvSum[b] / fmaxf(nf, 1.f);
        float ld = 0.f;
        for (int ii=0;ii<NL;ii++) for (int j=ii+1;j<NL;j++){
            if (pres[ii] && pres[j]){
                float d2=0.f;
                for (int d=0;d<4;d++){
                    float df = mean[ii][d]-mean[j][d];
                    d2 += df*df;
                }
                float pd = sqrtf(d2 + 1e-12f);
                float h = fmaxf(3.0f - pd, 0.f);
                ld += h*h;
            }
        }
        ld /= fmaxf(nf*(nf-1.f), 1.f);
        float lr = 0.f;
        for (int l=0;l<NL;l++){
            if (pres[l]){
                float d2=0.f;
                for (int d=0;d<4;d++) d2 += mean[l][d]*mean[l][d];
                lr += sqrtf(d2 + 1e-12f);
            }
        }
        lr /= fmaxf(nf, 1.f);
        float act = (n > 1) ? 1.f : 0.f;
        lvT += act*lv; ldT += act*ld; lrT += act*lr;
    }
    float loss_emb = 0.25f*(lvT + ldT + 0.001f*(lrT/(float)Bn));
    float loss = loss_k + 0.5f*loss_text + loss_emb;
    out[0]=loss; out[1]=loss_text; out[2]=loss_k; out[3]=loss_emb;
}

// ---------------- launch: fork 3 chains; streams created once, reused ------
extern "C" void kernel_launch(void* const* d_in, const int* in_sizes, int n_in,
                              void* d_out, int out_size){
    const float* pred   = (const float*)d_in[0];
    const float* gtText = (const float*)d_in[1];
    const float* gtk    = (const float*)d_in[2];
    const float* tm     = (const float*)d_in[3];
    const int*   inst   = (const int*)d_in[4];
    float* out = (float*)d_out;

    // one-time resource init (first call is the pre-baseline correctness run;
    // the capture call reuses these handles -> no allocation during capture)
    static cudaStream_t s1 = nullptr, s2 = nullptr;
    static cudaEvent_t ev0 = nullptr, ev1 = nullptr, ev2 = nullptr;
    static void* pS = nullptr;
    if (s1 == nullptr){
        cudaStreamCreateWithFlags(&s1, cudaStreamNonBlocking);
        cudaStreamCreateWithFlags(&s2, cudaStreamNonBlocking);
        cudaEventCreateWithFlags(&ev0, cudaEventDisableTiming);
        cudaEventCreateWithFlags(&ev1, cudaEventDisableTiming);
        cudaEventCreateWithFlags(&ev2, cudaEventDisableTiming);
        cudaGetSymbolAddress(&pS, gS);
    }

    cudaMemsetAsync(pS, 0, sizeof(Scal), 0);
    cudaEventRecord(ev0, 0);

    // chain A (s2): emb1 -> emb2
    cudaStreamWaitEvent(s2, ev0, 0);
    k_emb1<<<dim3(96, Bn), 128, 0, s2>>>(pred, inst, tm);
    k_emb2<<<3200, 256, 0, s2>>>(pred, inst, tm);
    cudaEventRecord(ev2, s2);

    // chain B (s1): dilstats -> select
    cudaStreamWaitEvent(s1, ev0, 0);
    k_dilstats<<<dim3(20,20,Bn), dim3(32,8), 0, s1>>>(pred, gtText, tm);
    k_selectAll<<<Bn, 1024, 0, s1>>>();
    cudaEventRecord(ev1, s1);

    // chain C (main): kern
    k_kern<<<3200, 256>>>(pred, gtk, tm);

    // join
    cudaStreamWaitEvent(0, ev1, 0);
    cudaStreamWaitEvent(0, ev2, 0);
    k_final<<<1, 32>>>(out);
}